// round 2
// baseline (speedup 1.0000x reference)
#include <cuda_runtime.h>

// packed f32x2 FMA (PTX-only; ptxas never emits FFMA2 from C++)
#define FMA2(d, a, b, c) \
    asm("fma.rn.f32x2 %0, %1, %2, %3;" : "=l"(d) : "l"(a), "l"(b), "l"(c))

namespace cfg {
constexpr int H = 224, Wd = 224, C = 32, O = 32;
constexpr int TLW = 32, TLH = 8;          // output tile per block
constexpr int CCH = 16;                   // channel chunk (== mask checkpoint)
constexpr int TR  = TLH + 2;              // 10 input rows
constexpr int TC  = TLW + 2;              // 34 input cols
constexpr int S2  = 34;                   // float2 row stride (even -> 16B rows; bank step 4)
constexpr int W2_ELEMS  = CCH * 9 * O;    // 4608 float2 (16ch of weights, duplicated)
constexpr int IN2_ELEMS = CCH * TR * S2;  // 5440 float2 (paired input tile)
constexpr int SMEM_BYTES = (W2_ELEMS + IN2_ELEMS) * 8;  // 80,384 B -> 2 blocks/SM
}

__global__ __launch_bounds__(256, 2)
void conv_early_kernel(const float* __restrict__ x,
                       const float* __restrict__ W,
                       float* __restrict__ out)
{
    using namespace cfg;
    extern __shared__ float2 sm2[];
    float2* w2  = sm2;               // [k = c*9+dy*3+dx][o], each entry (w,w)
    float2* in2 = sm2 + W2_ELEMS;    // [rowid = c*10+r][col] = (tile[col], tile[col+4])

    const int tid = threadIdx.x;
    const int x0  = blockIdx.x * TLW;
    const int y0  = blockIdx.y * TLH;
    const int b   = blockIdx.z;

    // mapping chosen so lanes 0-7 share xb (conflict-free LDS.128 phases)
    const int og  = tid >> 5;            // o-group: o = og*4 + 0..3
    const int xb  = (tid >> 3) & 3;      // x block of 8
    const int row = tid & 7;             // tile row

    unsigned long long acc[16];          // acc[o*4+pp] = f32x2 for pixels (pp, pp+4)
    #pragma unroll
    for (int i = 0; i < 16; i++) acc[i] = 0ull;
    unsigned mask = 0;

    const float* ximg = x + (size_t)b * C * H * Wd;

    #pragma unroll 1
    for (int stage = 0; stage < 2; stage++) {
        if (stage) __syncthreads();      // protect smem overwrite
        const int cbase = stage * CCH;

        // Stage 16 channels of weights, duplicated: w2[k*32+o] = (w,w).
        // gmem offset: o*288 + (cbase + k/9)*9 + k%9 == o*288 + cbase*9 + k.
        #pragma unroll 1
        for (int idx = tid; idx < W2_ELEMS; idx += 256) {
            int o = idx & 31;
            int k = idx >> 5;
            float w = W[o * (C * 9) + cbase * 9 + k];
            w2[idx] = make_float2(w, w);
        }

        // Paired input tile: one thread per (c, r) row; in2[col]=(v[col], v[col+4]).
        if (tid < CCH * TR) {
            int cl = tid / TR;
            int r  = tid - cl * TR;
            int gy = y0 - 1 + r;
            float v[TC];
            if ((unsigned)gy < (unsigned)H) {
                const float* xr = ximg + ((size_t)(cbase + cl) * H + gy) * Wd;
                v[0] = (x0 > 0) ? xr[x0 - 1] : 0.f;
                #pragma unroll
                for (int i = 0; i < 8; i++) {
                    float4 t = *reinterpret_cast<const float4*>(xr + x0 + i * 4);
                    v[1 + 4*i] = t.x; v[2 + 4*i] = t.y;
                    v[3 + 4*i] = t.z; v[4 + 4*i] = t.w;
                }
                v[33] = (x0 + 32 < Wd) ? xr[x0 + 32] : 0.f;
            } else {
                #pragma unroll
                for (int i = 0; i < TC; i++) v[i] = 0.f;
            }
            float2* dst = in2 + tid * S2;
            #pragma unroll
            for (int col = 0; col < TC; col++)
                dst[col] = make_float2(v[col], (col + 4 < TC) ? v[col + 4] : 0.f);
        }
        __syncthreads();

        const float2* irow0 = in2 + row * S2 + xb * 8;
        const float2* wbase = w2 + og * 4;

        #pragma unroll 2
        for (int c = 0; c < CCH; c++) {
            #pragma unroll
            for (int dy = 0; dy < 3; dy++) {
                const float2* ir = irow0 + (c * TR + dy) * S2;
                ulonglong2 A  = *reinterpret_cast<const ulonglong2*>(ir);
                ulonglong2 Bv = *reinterpret_cast<const ulonglong2*>(ir + 2);
                ulonglong2 Cv = *reinterpret_cast<const ulonglong2*>(ir + 4);
                unsigned long long P[6] = {A.x, A.y, Bv.x, Bv.y, Cv.x, Cv.y};

                const float2* wk = wbase + (c * 9 + dy * 3) * 32;
                #pragma unroll
                for (int dx = 0; dx < 3; dx++) {
                    ulonglong2 wA = *reinterpret_cast<const ulonglong2*>(wk + dx * 32);
                    ulonglong2 wB = *reinterpret_cast<const ulonglong2*>(wk + dx * 32 + 2);
                    unsigned long long wv[4] = {wA.x, wA.y, wB.x, wB.y};
                    #pragma unroll
                    for (int o = 0; o < 4; o++) {
                        #pragma unroll
                        for (int pp = 0; pp < 4; pp++)
                            FMA2(acc[o * 4 + pp], P[pp + dx], wv[o], acc[o * 4 + pp]);
                    }
                }
            }
        }

        if (stage == 0) {
            // checkpoint: sign of 16-channel partial per output element
            #pragma unroll
            for (int i = 0; i < 16; i++) {
                float lo = __uint_as_float((unsigned)(acc[i] & 0xffffffffull));
                float hi = __uint_as_float((unsigned)(acc[i] >> 32));
                mask |= (lo < 0.f ? 1u : 0u) << (2 * i);
                mask |= (hi < 0.f ? 1u : 0u) << (2 * i + 1);
            }
        }
    }

    // Epilogue: out = maskbit ? 0 : relu(full); float4 stores (gx0 32B aligned)
    const int gy  = y0 + row;
    const int gx0 = x0 + xb * 8;
    float* op = out + (((size_t)b * O + og * 4) * H + gy) * Wd + gx0;
    #pragma unroll
    for (int o = 0; o < 4; o++) {
        float lo[4], hi[4];
        #pragma unroll
        for (int pp = 0; pp < 4; pp++) {
            unsigned long long a = acc[o * 4 + pp];
            float l = __uint_as_float((unsigned)(a & 0xffffffffull));
            float h = __uint_as_float((unsigned)(a >> 32));
            int bi = 2 * (o * 4 + pp);
            lo[pp] = ((mask >> bi)       & 1u) ? 0.f : fmaxf(l, 0.f);
            hi[pp] = ((mask >> (bi + 1)) & 1u) ? 0.f : fmaxf(h, 0.f);
        }
        *reinterpret_cast<float4*>(op + (size_t)o * H * Wd)
            = make_float4(lo[0], lo[1], lo[2], lo[3]);
        *reinterpret_cast<float4*>(op + (size_t)o * H * Wd + 4)
            = make_float4(hi[0], hi[1], hi[2], hi[3]);
    }
}

extern "C" void kernel_launch(void* const* d_in, const int* in_sizes, int n_in,
                              void* d_out, int out_size)
{
    using namespace cfg;
    const float* x = (const float*)d_in[0];   // [32][32][224][224] f32
    const float* W = (const float*)d_in[1];   // [32][32][3][3] f32
    float* out = (float*)d_out;

    cudaFuncSetAttribute(conv_early_kernel,
                         cudaFuncAttributeMaxDynamicSharedMemorySize, SMEM_BYTES);
    dim3 grid(Wd / TLW, H / TLH, 32);         // 7 x 28 x 32
    conv_early_kernel<<<grid, 256, SMEM_BYTES>>>(x, W, out);
}

// round 3
// speedup vs baseline: 1.1351x; 1.1351x over previous
#include <cuda_runtime.h>

// packed f32x2 FMA (PTX-only; ptxas never emits FFMA2 from C++)
#define FMA2(d, a, b, c) \
    asm("fma.rn.f32x2 %0, %1, %2, %3;" : "=l"(d) : "l"(a), "l"(b), "l"(c))

namespace cfg {
constexpr int H = 224, Wd = 224, C = 32, O = 32;
constexpr int TLW = 32, TLH = 16;         // output tile per block
constexpr int CCH = 8;                    // channel chunk (4 stages; checkpoint after 2)
constexpr int TR  = TLH + 2;              // 18 input rows
constexpr int TC  = TLW + 2;              // 34 input cols
constexpr int S2  = 34;                   // float2 row stride (bank step 4 per row)
constexpr int OPT = 8;                    // o-channels per thread
constexpr int W2_ELEMS  = CCH * 9 * O;    // 2304 float2 (8ch weights, duplicated)
constexpr int IN2_ELEMS = CCH * TR * S2;  // 4896 float2 (paired input tile)
constexpr int SMEM_BYTES = (W2_ELEMS + IN2_ELEMS) * 8;  // 57,600 B -> 2 blocks/SM
}

__global__ __launch_bounds__(256, 2)
void conv_early_kernel(const float* __restrict__ x,
                       const float* __restrict__ W,
                       float* __restrict__ out)
{
    using namespace cfg;
    extern __shared__ float2 sm2[];
    float2* w2  = sm2;               // [k = c*9+dy*3+dx][o], each entry (w,w)
    float2* in2 = sm2 + W2_ELEMS;    // [c*18+r][col] = (tile[col], tile[col+4])

    const int tid = threadIdx.x;
    const int x0  = blockIdx.x * TLW;
    const int y0  = blockIdx.y * TLH;
    const int b   = blockIdx.z;

    // og-group of 64 threads: row = idx&15, xb = (idx>>4)&3.
    // Every 8-lane LDS.128 phase covers 32 distinct banks (bank = 4*row+16*xb+j).
    const int og  = tid >> 6;            // 0..3 -> o = og*8 + 0..7
    const int idx = tid & 63;
    const int row = idx & 15;
    const int xb  = (idx >> 4) & 3;      // x block of 8

    unsigned long long acc[32];          // acc[o*4+pp] = f32x2 for pixels (pp, pp+4)
    #pragma unroll
    for (int i = 0; i < 32; i++) acc[i] = 0ull;
    unsigned long long mask = 0;         // 64 early-terminate sign bits

    const float* ximg = x + (size_t)b * C * H * Wd;

    #pragma unroll 1
    for (int stage = 0; stage < 4; stage++) {
        if (stage) __syncthreads();      // protect smem overwrite
        const int cbase = stage * CCH;

        // Stage 8 channels of weights, duplicated: w2[k*32+o] = (w,w).
        if (tid < W2_ELEMS / 9 * 9) {}   // (no-op; keep full 256-thread loop below)
        #pragma unroll 1
        for (int i = tid; i < W2_ELEMS; i += 256) {
            int o = i & 31;
            int k = i >> 5;              // c*9+dy*3+dx within this 8-channel chunk
            float w = W[o * (C * 9) + cbase * 9 + k];
            w2[i] = make_float2(w, w);
        }

        // Paired input tile: one thread per (c, r) row; in2[col]=(v[col], v[col+4]).
        if (tid < CCH * TR) {            // 144 row-threads
            int cl = tid / TR;
            int r  = tid - cl * TR;
            int gy = y0 - 1 + r;
            float v[TC];
            if ((unsigned)gy < (unsigned)H) {
                const float* xr = ximg + ((size_t)(cbase + cl) * H + gy) * Wd;
                v[0] = (x0 > 0) ? xr[x0 - 1] : 0.f;
                #pragma unroll
                for (int i2 = 0; i2 < 8; i2++) {
                    float4 t = *reinterpret_cast<const float4*>(xr + x0 + i2 * 4);
                    v[1 + 4*i2] = t.x; v[2 + 4*i2] = t.y;
                    v[3 + 4*i2] = t.z; v[4 + 4*i2] = t.w;
                }
                v[33] = (x0 + 32 < Wd) ? xr[x0 + 32] : 0.f;
            } else {
                #pragma unroll
                for (int i2 = 0; i2 < TC; i2++) v[i2] = 0.f;
            }
            float2* dst = in2 + tid * S2;
            #pragma unroll
            for (int col = 0; col < TC; col++)
                dst[col] = make_float2(v[col], (col + 4 < TC) ? v[col + 4] : 0.f);
        }
        __syncthreads();

        const float2* irow0 = in2 + row * S2 + xb * 8;
        const float2* wbase = w2 + og * OPT;

        #pragma unroll 2
        for (int c = 0; c < CCH; c++) {
            #pragma unroll
            for (int dy = 0; dy < 3; dy++) {
                const float2* ir = irow0 + (c * TR + dy) * S2;
                ulonglong2 A  = *reinterpret_cast<const ulonglong2*>(ir);
                ulonglong2 Bv = *reinterpret_cast<const ulonglong2*>(ir + 2);
                ulonglong2 Cv = *reinterpret_cast<const ulonglong2*>(ir + 4);
                unsigned long long P[6] = {A.x, A.y, Bv.x, Bv.y, Cv.x, Cv.y};

                const float2* wk = wbase + (c * 9 + dy * 3) * 32;
                #pragma unroll
                for (int dx = 0; dx < 3; dx++) {
                    ulonglong2 wA = *reinterpret_cast<const ulonglong2*>(wk + dx * 32);
                    ulonglong2 wB = *reinterpret_cast<const ulonglong2*>(wk + dx * 32 + 2);
                    ulonglong2 wC = *reinterpret_cast<const ulonglong2*>(wk + dx * 32 + 4);
                    ulonglong2 wD = *reinterpret_cast<const ulonglong2*>(wk + dx * 32 + 6);
                    unsigned long long wv[8] = {wA.x, wA.y, wB.x, wB.y,
                                                wC.x, wC.y, wD.x, wD.y};
                    #pragma unroll
                    for (int o = 0; o < OPT; o++) {
                        #pragma unroll
                        for (int pp = 0; pp < 4; pp++)
                            FMA2(acc[o * 4 + pp], P[pp + dx], wv[o], acc[o * 4 + pp]);
                    }
                }
            }
        }

        if (stage == 1) {
            // checkpoint: sign of 16-channel partial per output element
            #pragma unroll
            for (int i2 = 0; i2 < 32; i2++) {
                float lo = __uint_as_float((unsigned)(acc[i2] & 0xffffffffull));
                float hi = __uint_as_float((unsigned)(acc[i2] >> 32));
                mask |= (unsigned long long)(lo < 0.f ? 1u : 0u) << (2 * i2);
                mask |= (unsigned long long)(hi < 0.f ? 1u : 0u) << (2 * i2 + 1);
            }
        }
    }

    // Epilogue: out = maskbit ? 0 : relu(full); float4 stores (gx0 32B aligned)
    const int gy  = y0 + row;
    const int gx0 = x0 + xb * 8;
    float* op = out + (((size_t)b * O + og * OPT) * H + gy) * Wd + gx0;
    #pragma unroll
    for (int o = 0; o < OPT; o++) {
        float lo[4], hi[4];
        #pragma unroll
        for (int pp = 0; pp < 4; pp++) {
            unsigned long long a = acc[o * 4 + pp];
            float l = __uint_as_float((unsigned)(a & 0xffffffffull));
            float h = __uint_as_float((unsigned)(a >> 32));
            int bi = 2 * (o * 4 + pp);
            lo[pp] = ((mask >> bi)       & 1ull) ? 0.f : fmaxf(l, 0.f);
            hi[pp] = ((mask >> (bi + 1)) & 1ull) ? 0.f : fmaxf(h, 0.f);
        }
        *reinterpret_cast<float4*>(op + (size_t)o * H * Wd)
            = make_float4(lo[0], lo[1], lo[2], lo[3]);
        *reinterpret_cast<float4*>(op + (size_t)o * H * Wd + 4)
            = make_float4(hi[0], hi[1], hi[2], hi[3]);
    }
}

extern "C" void kernel_launch(void* const* d_in, const int* in_sizes, int n_in,
                              void* d_out, int out_size)
{
    using namespace cfg;
    const float* x = (const float*)d_in[0];   // [32][32][224][224] f32
    const float* W = (const float*)d_in[1];   // [32][32][3][3] f32
    float* out = (float*)d_out;

    cudaFuncSetAttribute(conv_early_kernel,
                         cudaFuncAttributeMaxDynamicSharedMemorySize, SMEM_BYTES);
    dim3 grid(Wd / TLW, H / TLH, 32);         // 7 x 14 x 32 = 3136 blocks
    conv_early_kernel<<<grid, 256, SMEM_BYTES>>>(x, W, out);
}

// round 5
// speedup vs baseline: 1.1403x; 1.0046x over previous
#include <cuda_runtime.h>

// packed f32x2 FMA (PTX-only; ptxas never emits FFMA2 from C++)
#define FMA2(d, a, b, c) \
    asm("fma.rn.f32x2 %0, %1, %2, %3;" : "=l"(d) : "l"(a), "l"(b), "l"(c))

namespace cfg {
constexpr int H = 224, Wd = 224, C = 32, O = 32;
constexpr int TLW = 32, TLH = 16;     // output tile
constexpr int CCH = 8;                // channels per stage (4 stages; checkpoint after 2)
constexpr int TR  = 18;               // input rows per channel (16 + halo)
constexpr int S2  = 34;               // f32x2 per tile row ((v,v) duplicated, cols -1..32)
constexpr int BUF = CCH * TR * S2;    // 4896 f32x2 per buffer
constexpr int SMEM_BYTES = 2 * BUF * 8;  // 78,336 B double-buffered -> 2 blocks/SM
constexpr int KW = C * 9;             // 288 taps per output channel
}

// weights packed as (W[o][k], W[o+16][k]) pairs, op-major per k: c_w[k*16 + op]
__device__ float2 g_wtmp[cfg::KW * 16];
__constant__ float2 c_w[cfg::KW * 16];

__global__ void weight_pack_kernel(const float* __restrict__ W)
{
    int i = blockIdx.x * 256 + threadIdx.x;
    if (i < cfg::KW * 16) {
        int k = i >> 4, op = i & 15;
        g_wtmp[i] = make_float2(W[op * cfg::KW + k], W[(op + 16) * cfg::KW + k]);
    }
}

__global__ __launch_bounds__(256, 2)
void conv_early_kernel(const float* __restrict__ x, float* __restrict__ out)
{
    using namespace cfg;
    extern __shared__ float2 sbuf[];     // two BUF-sized input buffers

    const int tid = threadIdx.x;
    const int wpw = tid >> 5;            // warp 0..7: stages channel c = wpw
    const int l   = tid & 31;
    const int og  = tid >> 7;            // 0..1: o set og*8..og*8+7 (paired with +16)
    const int idx = tid & 127;
    const int rr  = idx & 15;            // output row in tile
    const int xq  = (idx >> 4) & 7;      // x quad (4 px)

    const int x0 = blockIdx.x * TLW;
    const int y0 = blockIdx.y * TLH;
    const int b  = blockIdx.z;
    const float* ximg = x + (size_t)b * C * H * Wd;

    const bool colA_ok = (unsigned)(x0 - 1 + l) < (unsigned)Wd;  // lane0 @ x0==0 fails only
    const bool colB_ok = (l < 2) && ((unsigned)(x0 + 31 + l) < (unsigned)Wd);

    unsigned long long acc[32];          // acc[opl*4+px] = (out[o], out[o+16])
    #pragma unroll
    for (int i = 0; i < 32; i++) acc[i] = 0ull;
    unsigned long long mask = 0;

    float vA[9], vB[9];
    const ulonglong2* cw2 = reinterpret_cast<const ulonglong2*>(c_w);

    // ---- staging helpers (warp wpw stages channel c=wpw of each stage) ----
    auto ldg_half = [&](int stage, int half) {
        const float* cp = ximg + (size_t)(stage * CCH + wpw) * H * Wd;
        #pragma unroll
        for (int k = 0; k < 9; k++) {
            int r  = half * 9 + k;
            int gy = y0 - 1 + r;
            bool row_ok = (unsigned)gy < (unsigned)H;
            const float* rp = cp + (size_t)gy * Wd;
            vA[k] = (row_ok && colA_ok) ? rp[x0 - 1 + l] : 0.f;
            vB[k] = (row_ok && colB_ok) ? rp[x0 + 31 + l] : 0.f;
        }
    };
    auto sts_half = [&](int half, float2* buf) {
        #pragma unroll
        for (int k = 0; k < 9; k++) {
            int r = half * 9 + k;
            float2* dst = buf + (wpw * TR + r) * S2;
            dst[l] = make_float2(vA[k], vA[k]);
            if (l < 2) dst[32 + l] = make_float2(vB[k], vB[k]);
        }
    };

    // ---- prologue: stage 0 ----
    ldg_half(0, 0); sts_half(0, sbuf);
    ldg_half(0, 1); sts_half(1, sbuf);

    #pragma unroll 1
    for (int stage = 0; stage < 4; stage++) {
        float2* cur = sbuf + (stage & 1) * BUF;
        float2* nxt = sbuf + ((stage + 1) & 1) * BUF;
        __syncthreads();                 // cur complete; prior readers of nxt done

        #pragma unroll 1
        for (int half = 0; half < 2; half++) {
            if (stage < 3) ldg_half(stage + 1, half);

            #pragma unroll 1
            for (int cl = half * 4; cl < half * 4 + 4; cl++) {
                const int cg = stage * CCH + cl;          // global channel
                const int kb = cg * 72 + og * 4;          // cw2 base (9 taps * 8 pairs)
                #pragma unroll
                for (int dy = 0; dy < 3; dy++) {
                    const ulonglong2* ir = reinterpret_cast<const ulonglong2*>(
                        cur + (cl * TR + rr + dy) * S2 + 4 * xq);
                    ulonglong2 A = ir[0], B = ir[1], Cv = ir[2];
                    unsigned long long P[6] = {A.x, A.y, B.x, B.y, Cv.x, Cv.y};
                    #pragma unroll
                    for (int dx = 0; dx < 3; dx++) {
                        #pragma unroll
                        for (int j = 0; j < 4; j++) {
                            ulonglong2 wp = cw2[kb + dy * 24 + dx * 8 + j];
                            #pragma unroll
                            for (int px = 0; px < 4; px++)
                                FMA2(acc[(2*j+0)*4 + px], P[px + dx], wp.x,
                                     acc[(2*j+0)*4 + px]);
                            #pragma unroll
                            for (int px = 0; px < 4; px++)
                                FMA2(acc[(2*j+1)*4 + px], P[px + dx], wp.y,
                                     acc[(2*j+1)*4 + px]);
                        }
                    }
                }
            }
            if (stage < 3) sts_half(half, nxt);
        }

        if (stage == 1) {
            // 16-channel checkpoint: sign of partial sum per output element
            #pragma unroll
            for (int i = 0; i < 32; i++) {
                float lo = __uint_as_float((unsigned)(acc[i] & 0xffffffffull));
                float hi = __uint_as_float((unsigned)(acc[i] >> 32));
                mask |= (unsigned long long)(lo < 0.f ? 1u : 0u) << (2 * i);
                mask |= (unsigned long long)(hi < 0.f ? 1u : 0u) << (2 * i + 1);
            }
        }
    }

    // ---- epilogue: out = maskbit ? 0 : relu(full) ----
    const int gy  = y0 + rr;
    const int gx0 = x0 + 4 * xq;
    #pragma unroll
    for (int opl = 0; opl < 8; opl++) {
        int o = og * 8 + opl;
        float lo[4], hi[4];
        #pragma unroll
        for (int px = 0; px < 4; px++) {
            unsigned long long a = acc[opl * 4 + px];
            float lv = __uint_as_float((unsigned)(a & 0xffffffffull));
            float hv = __uint_as_float((unsigned)(a >> 32));
            int bi = 2 * (opl * 4 + px);
            lo[px] = ((mask >> bi)       & 1ull) ? 0.f : fmaxf(lv, 0.f);
            hi[px] = ((mask >> (bi + 1)) & 1ull) ? 0.f : fmaxf(hv, 0.f);
        }
        float* p0 = out + (((size_t)b * O + o)      * H + gy) * Wd + gx0;
        float* p1 = out + (((size_t)b * O + o + 16) * H + gy) * Wd + gx0;
        *reinterpret_cast<float4*>(p0) = make_float4(lo[0], lo[1], lo[2], lo[3]);
        *reinterpret_cast<float4*>(p1) = make_float4(hi[0], hi[1], hi[2], hi[3]);
    }
}

extern "C" void kernel_launch(void* const* d_in, const int* in_sizes, int n_in,
                              void* d_out, int out_size)
{
    using namespace cfg;
    const float* x = (const float*)d_in[0];   // [32][32][224][224] f32
    const float* W = (const float*)d_in[1];   // [32][32][3][3] f32
    float* out = (float*)d_out;

    // 1) pack weights into (o, o+16) f32x2 pairs in global scratch
    weight_pack_kernel<<<(KW * 16 + 255) / 256, 256>>>(W);

    // 2) copy into the constant bank. Resolve REAL device addresses of both
    //    symbols (the R4 bug: passing a __device__ symbol name as a host
    //    pointer). cudaGetSymbolAddress is a query, not an allocation.
    void* src = nullptr; void* dst = nullptr;
    cudaGetSymbolAddress(&src, g_wtmp);
    cudaGetSymbolAddress(&dst, c_w);
    cudaMemcpyAsync(dst, src, sizeof(float2) * KW * 16, cudaMemcpyDeviceToDevice);

    // 3) main conv
    cudaFuncSetAttribute(conv_early_kernel,
                         cudaFuncAttributeMaxDynamicSharedMemorySize, SMEM_BYTES);
    dim3 grid(Wd / TLW, H / TLH, 32);         // 7 x 14 x 32
    conv_early_kernel<<<grid, 256, SMEM_BYTES>>>(x, out);
}